// round 1
// baseline (speedup 1.0000x reference)
#include <cuda_runtime.h>

#define NN 50000
#define NE 640000
#define D  128
#define NL 5
#define NG 512
#define NC 128

// ---------------- scratch (static device globals; no runtime alloc) --------
__device__ __align__(16) float g_h[NN * D];
__device__ __align__(16) float g_u[NN * D];
__device__ __align__(16) float g_v[NN * D];
__device__ float g_invdeg[NN];
__device__ float g_c[NN];
__device__ int   g_indeg[NN];
__device__ int   g_rowptr[NN + 1];
__device__ int   g_fill[NN];
__device__ int   g_csr_src[NE];
__device__ int   g_csr_eid[NE];
__device__ __align__(16) float g_pooled[NG * D];
__device__ int   g_gcnt[NG];

// ---------------- init / CSR build -----------------------------------------
__global__ void k_zero() {
    int i = blockIdx.x * blockDim.x + threadIdx.x;
    if (i < NN) { g_indeg[i] = 0; g_fill[i] = 0; }
    if (i < NG * D) g_pooled[i] = 0.f;
    if (i < NG) g_gcnt[i] = 0;
}

__global__ void k_count(const int* __restrict__ ei) {
    int e = blockIdx.x * blockDim.x + threadIdx.x;
    if (e < NE) atomicAdd(&g_indeg[ei[NE + e]], 1);
}

// single-block exclusive scan of indeg -> rowptr; also invdeg / c
__global__ void k_scan() {
    __shared__ int warp_sums[32];
    __shared__ int s_off;
    int tid = threadIdx.x, lane = tid & 31, wid = tid >> 5;
    if (tid == 0) s_off = 0;
    __syncthreads();
    for (int base = 0; base < NN; base += 1024) {
        int i = base + tid;
        int v = (i < NN) ? g_indeg[i] : 0;
        int x = v;
#pragma unroll
        for (int s = 1; s < 32; s <<= 1) {
            int t = __shfl_up_sync(0xffffffffu, x, s);
            if (lane >= s) x += t;
        }
        if (lane == 31) warp_sums[wid] = x;
        __syncthreads();
        if (wid == 0) {
            int y = warp_sums[lane];
#pragma unroll
            for (int s = 1; s < 32; s <<= 1) {
                int t = __shfl_up_sync(0xffffffffu, y, s);
                if (lane >= s) y += t;
            }
            warp_sums[lane] = y;
        }
        __syncthreads();
        if (i < NN) {
            int excl = s_off + (wid > 0 ? warp_sums[wid - 1] : 0) + x - v;
            g_rowptr[i] = excl;
            g_invdeg[i] = 1.0f / fmaxf((float)v, 1.0f);
            g_c[i] = (v > 0) ? 2.0f : 1.0f;
        }
        __syncthreads();
        if (tid == 1023) s_off += warp_sums[31];
        __syncthreads();
    }
    if (threadIdx.x == 0) g_rowptr[NN] = s_off;
}

__global__ void k_fill(const int* __restrict__ ei) {
    int e = blockIdx.x * blockDim.x + threadIdx.x;
    if (e < NE) {
        int dst = ei[NE + e];
        int p = g_rowptr[dst] + atomicAdd(&g_fill[dst], 1);
        g_csr_src[p] = ei[e];
        g_csr_eid[p] = e;
    }
}

// V[i] = (sum_{e->i} edge_attr[e]) / deg[i]   — one warp per node
__global__ void k_v(const float* __restrict__ ea) {
    int gt = blockIdx.x * blockDim.x + threadIdx.x;
    int w = gt >> 5, lane = gt & 31;
    if (w >= NN) return;
    int s = g_rowptr[w], t = g_rowptr[w + 1];
    float4 acc = make_float4(0.f, 0.f, 0.f, 0.f);
    const float4* ea4 = (const float4*)ea;
    int p = s;
    for (; p + 1 < t; p += 2) {
        int e0 = g_csr_eid[p], e1 = g_csr_eid[p + 1];
        float4 x0 = ea4[e0 * 32 + lane];
        float4 x1 = ea4[e1 * 32 + lane];
        acc.x += x0.x + x1.x; acc.y += x0.y + x1.y;
        acc.z += x0.z + x1.z; acc.w += x0.w + x1.w;
    }
    if (p < t) {
        int e0 = g_csr_eid[p];
        float4 x0 = ea4[e0 * 32 + lane];
        acc.x += x0.x; acc.y += x0.y; acc.z += x0.z; acc.w += x0.w;
    }
    float id = g_invdeg[w];
    acc.x *= id; acc.y *= id; acc.z *= id; acc.w *= id;
    ((float4*)g_v)[w * 32 + lane] = acc;
}

// layer-0 shortcut: u = c[i] * node_emb[x[i]]   (h0 is rank-1, S·h0 = indeg·h0)
__global__ void k_u0(const float* __restrict__ emb, const int* __restrict__ x) {
    int i = blockIdx.x * blockDim.x + threadIdx.x;
    if (i >= NN * 32) return;
    int node = i >> 5, q = i & 31;
    float4 e = ((const float4*)emb)[x[node] * 32 + q];
    float c = g_c[node];
    e.x *= c; e.y *= c; e.z *= c; e.w *= c;
    ((float4*)g_u)[i] = e;
}

// u[i] = h[i] + (sum_{e->i} h[src_e]) / deg[i]   — one warp per node
__global__ void k_spmm() {
    int gt = blockIdx.x * blockDim.x + threadIdx.x;
    int w = gt >> 5, lane = gt & 31;
    if (w >= NN) return;
    int s = g_rowptr[w], t = g_rowptr[w + 1];
    float4 acc = make_float4(0.f, 0.f, 0.f, 0.f);
    const float4* h4 = (const float4*)g_h;
    int p = s;
    for (; p + 1 < t; p += 2) {
        int s0 = g_csr_src[p], s1 = g_csr_src[p + 1];
        float4 x0 = h4[s0 * 32 + lane];
        float4 x1 = h4[s1 * 32 + lane];
        acc.x += x0.x + x1.x; acc.y += x0.y + x1.y;
        acc.z += x0.z + x1.z; acc.w += x0.w + x1.w;
    }
    if (p < t) {
        int s0 = g_csr_src[p];
        float4 x0 = h4[s0 * 32 + lane];
        acc.x += x0.x; acc.y += x0.y; acc.z += x0.z; acc.w += x0.w;
    }
    float id = g_invdeg[w];
    float4 hh = h4[w * 32 + lane];
    acc.x = hh.x + acc.x * id; acc.y = hh.y + acc.y * id;
    acc.z = hh.z + acc.z * id; acc.w = hh.w + acc.w * id;
    ((float4*)g_u)[w * 32 + lane] = acc;
}

// h = act( [u | v] @ [W ; We] + c * b )  — M=50000, K=256, N=128
// BM=64, BN=128, BK=16, 128 threads, each 8x8 micro-tile
#define BM 64
#define BK 16
__global__ __launch_bounds__(128) void k_gemm(
    const float* __restrict__ W, const float* __restrict__ We,
    const float* __restrict__ bias, int relu)
{
    __shared__ float As[BK][BM + 4];
    __shared__ float Bs[BK][D];
    __shared__ float sb[D];
    int tid = threadIdx.x;
    int row0 = blockIdx.x * BM;
    sb[tid] = bias[tid];
    int tr = tid >> 4, tc = tid & 15;
    int lm = tid >> 2, lk = (tid & 3) * 4;
    float acc[8][8];
#pragma unroll
    for (int r = 0; r < 8; r++)
#pragma unroll
        for (int c = 0; c < 8; c++) acc[r][c] = 0.f;

#pragma unroll 1
    for (int kt = 0; kt < 16; kt++) {
        const float* Asrc = (kt < 8) ? g_u : g_v;
        const float* Bsrc = (kt < 8) ? W : We;
        int kb = (kt & 7) * BK;
        __syncthreads();
        // A tile: 64 rows x 16 k (transposed into smem)
#pragma unroll
        for (int hh = 0; hh < 2; hh++) {
            int m = lm + hh * 32;
            int row = row0 + m;
            float4 a = (row < NN) ? ((const float4*)Asrc)[row * 32 + ((kb + lk) >> 2)]
                                  : make_float4(0.f, 0.f, 0.f, 0.f);
            As[lk + 0][m] = a.x; As[lk + 1][m] = a.y;
            As[lk + 2][m] = a.z; As[lk + 3][m] = a.w;
        }
        // B tile: 16 k x 128 n
#pragma unroll
        for (int j = 0; j < 4; j++) {
            int idx = tid + 128 * j;
            int k = idx >> 5, n4 = idx & 31;
            *(float4*)&Bs[k][n4 * 4] = ((const float4*)Bsrc)[(kb + k) * 32 + n4];
        }
        __syncthreads();
#pragma unroll
        for (int k = 0; k < BK; k++) {
            float a[8], b[8];
            *(float4*)&a[0] = *(float4*)&As[k][tr * 8];
            *(float4*)&a[4] = *(float4*)&As[k][tr * 8 + 4];
            *(float4*)&b[0] = *(float4*)&Bs[k][tc * 8];
            *(float4*)&b[4] = *(float4*)&Bs[k][tc * 8 + 4];
#pragma unroll
            for (int r = 0; r < 8; r++)
#pragma unroll
                for (int c = 0; c < 8; c++) acc[r][c] = fmaf(a[r], b[c], acc[r][c]);
        }
    }
    // epilogue: + c*b, relu, store
#pragma unroll
    for (int r = 0; r < 8; r++) {
        int row = row0 + tr * 8 + r;
        if (row >= NN) continue;
        float cf = g_c[row];
        float o[8];
#pragma unroll
        for (int c = 0; c < 8; c++) {
            float v = acc[r][c] + cf * sb[tc * 8 + c];
            o[c] = relu ? fmaxf(v, 0.f) : v;
        }
        ((float4*)g_h)[row * 32 + tc * 2 + 0] = *(float4*)&o[0];
        ((float4*)g_h)[row * 32 + tc * 2 + 1] = *(float4*)&o[4];
    }
}

// ---------------- pooling + classifier -------------------------------------
__global__ void k_pool(const int* __restrict__ batch) {
    int t = blockIdx.x * blockDim.x + threadIdx.x;
    if (t >= NN * 32) return;
    int i = t >> 5, q = t & 31;
    int g = batch[i];
    float4 h4 = ((const float4*)g_h)[t];
    atomicAdd(&g_pooled[g * D + q * 4 + 0], h4.x);
    atomicAdd(&g_pooled[g * D + q * 4 + 1], h4.y);
    atomicAdd(&g_pooled[g * D + q * 4 + 2], h4.z);
    atomicAdd(&g_pooled[g * D + q * 4 + 3], h4.w);
    if (q == 0) atomicAdd(&g_gcnt[i >> 5 == i >> 5 ? g : g], 1);
}

__global__ void k_out(const float* __restrict__ Wp, const float* __restrict__ bp,
                      float* __restrict__ out) {
    int g = blockIdx.x, t = threadIdx.x;
    __shared__ float sp[D];
    float inv = 1.f / fmaxf((float)g_gcnt[g], 1.f);
    sp[t] = g_pooled[g * D + t] * inv;
    __syncthreads();
    float acc = bp[t];
#pragma unroll 8
    for (int k = 0; k < D; k++) acc = fmaf(sp[k], Wp[k * NC + t], acc);
    out[g * NC + t] = acc;
}

// ---------------- launch ----------------------------------------------------
extern "C" void kernel_launch(void* const* d_in, const int* in_sizes, int n_in,
                              void* d_out, int out_size) {
    const int*   x     = (const int*)d_in[0];
    const int*   ei    = (const int*)d_in[1];
    const float* ea    = (const float*)d_in[2];
    const int*   batch = (const int*)d_in[3];
    const float* emb   = (const float*)d_in[4];
    const float* Ws    = (const float*)d_in[5];
    const float* bs    = (const float*)d_in[6];
    const float* Wes   = (const float*)d_in[7];
    const float* Wp    = (const float*)d_in[8];
    const float* bp    = (const float*)d_in[9];
    float* out = (float*)d_out;

    k_zero<<<(NG * D + 255) / 256, 256>>>();
    k_count<<<(NE + 255) / 256, 256>>>(ei);
    k_scan<<<1, 1024>>>();
    k_fill<<<(NE + 255) / 256, 256>>>(ei);
    k_v<<<(NN * 32 + 255) / 256, 256>>>(ea);
    k_u0<<<(NN * 32 + 255) / 256, 256>>>(emb, x);
    for (int l = 0; l < NL; l++) {
        if (l > 0) k_spmm<<<(NN * 32 + 255) / 256, 256>>>();
        k_gemm<<<(NN + BM - 1) / BM, 128>>>(Ws + l * D * D, Wes + l * D * D,
                                            bs + l * D, l < NL - 1 ? 1 : 0);
    }
    k_pool<<<(NN * 32 + 255) / 256, 256>>>(batch);
    k_out<<<NG, D>>>(Wp, bp, out);
}

// round 2
// speedup vs baseline: 1.7190x; 1.7190x over previous
#include <cuda_runtime.h>
#include <cuda_bf16.h>
#include <cstdint>

#define NN 50000
#define NE 640000
#define D  128
#define NL 5
#define NG 512
#define NC 128
#define NBLK ((NN + 255) / 256)

// ---------------- scratch (static device globals) --------------------------
__device__ __align__(16) float g_h[NN * D];
__device__ __align__(16) __nv_bfloat16 g_uhi[NN * D];
__device__ __align__(16) __nv_bfloat16 g_ulo[NN * D];
__device__ __align__(16) __nv_bfloat16 g_vhi[NN * D];
__device__ __align__(16) __nv_bfloat16 g_vlo[NN * D];
__device__ __align__(16) __nv_bfloat16 g_Whi[NL * 256 * 128];
__device__ __align__(16) __nv_bfloat16 g_Wlo[NL * 256 * 128];
__device__ float g_invdeg[NN];
__device__ float g_c[NN];
__device__ int   g_indeg[NN];
__device__ int   g_rowptr[NN + 1];
__device__ int   g_fill[NN];
__device__ int   g_bsum[NBLK + 32];
__device__ int   g_csr_src[NE];
__device__ int   g_csr_eid[NE];

// ---------------- helpers ---------------------------------------------------
__device__ __forceinline__ unsigned short bf_bits(__nv_bfloat16 h) {
    unsigned short u; memcpy(&u, &h, 2); return u;
}
__device__ __forceinline__ void split4(float4 a, uint2& hi, uint2& lo) {
    __nv_bfloat16 h0 = __float2bfloat16(a.x), h1 = __float2bfloat16(a.y);
    __nv_bfloat16 h2 = __float2bfloat16(a.z), h3 = __float2bfloat16(a.w);
    __nv_bfloat16 l0 = __float2bfloat16(a.x - __bfloat162float(h0));
    __nv_bfloat16 l1 = __float2bfloat16(a.y - __bfloat162float(h1));
    __nv_bfloat16 l2 = __float2bfloat16(a.z - __bfloat162float(h2));
    __nv_bfloat16 l3 = __float2bfloat16(a.w - __bfloat162float(h3));
    hi.x = (unsigned)bf_bits(h0) | ((unsigned)bf_bits(h1) << 16);
    hi.y = (unsigned)bf_bits(h2) | ((unsigned)bf_bits(h3) << 16);
    lo.x = (unsigned)bf_bits(l0) | ((unsigned)bf_bits(l1) << 16);
    lo.y = (unsigned)bf_bits(l2) | ((unsigned)bf_bits(l3) << 16);
}
__device__ __forceinline__ uint32_t sptr(const void* p) {
    return (uint32_t)__cvta_generic_to_shared(p);
}

#define LDSM4(R, addr) \
    asm volatile("ldmatrix.sync.aligned.m8n8.x4.shared.b16 {%0,%1,%2,%3},[%4];" \
        : "=r"((R)[0]), "=r"((R)[1]), "=r"((R)[2]), "=r"((R)[3]) : "r"(addr))
#define LDSM4T(R, addr) \
    asm volatile("ldmatrix.sync.aligned.m8n8.x4.trans.shared.b16 {%0,%1,%2,%3},[%4];" \
        : "=r"((R)[0]), "=r"((R)[1]), "=r"((R)[2]), "=r"((R)[3]) : "r"(addr))
#define MMA(C, A, B) \
    asm volatile("mma.sync.aligned.m16n8k16.row.col.f32.bf16.bf16.f32 " \
        "{%0,%1,%2,%3},{%4,%5,%6,%7},{%8,%9},{%0,%1,%2,%3};" \
        : "+f"((C)[0]), "+f"((C)[1]), "+f"((C)[2]), "+f"((C)[3]) \
        : "r"((A)[0]), "r"((A)[1]), "r"((A)[2]), "r"((A)[3]), "r"((B)[0]), "r"((B)[1]))

// ---------------- init / CSR build -----------------------------------------
__global__ void k_zero() {
    int i = blockIdx.x * blockDim.x + threadIdx.x;
    if (i < NN) { g_indeg[i] = 0; g_fill[i] = 0; }
}

__global__ void k_count(const int* __restrict__ ei) {
    int e = blockIdx.x * blockDim.x + threadIdx.x;
    if (e < NE) atomicAdd(&g_indeg[ei[NE + e]], 1);
}

// scan stage 1: per-block sums
__global__ void k_scan1() {
    __shared__ int sm[8];
    int t = threadIdx.x, lane = t & 31, wid = t >> 5;
    int i = blockIdx.x * 256 + t;
    int v = (i < NN) ? g_indeg[i] : 0;
#pragma unroll
    for (int s = 16; s > 0; s >>= 1) v += __shfl_down_sync(0xffffffffu, v, s);
    if (lane == 0) sm[wid] = v;
    __syncthreads();
    if (t == 0) {
        int s = 0;
#pragma unroll
        for (int w = 0; w < 8; w++) s += sm[w];
        g_bsum[blockIdx.x] = s;
    }
}

// scan stage 2: single block scans block sums
__global__ void k_scan2() {
    __shared__ int ws[8];
    int t = threadIdx.x, lane = t & 31, wid = t >> 5;
    int v = (t < NBLK) ? g_bsum[t] : 0;
    int x = v;
#pragma unroll
    for (int s = 1; s < 32; s <<= 1) {
        int tt = __shfl_up_sync(0xffffffffu, x, s);
        if (lane >= s) x += tt;
    }
    if (lane == 31) ws[wid] = x;
    __syncthreads();
    if (t == 0) {
        int acc = 0;
#pragma unroll
        for (int w = 0; w < 8; w++) { int tmp = ws[w]; ws[w] = acc; acc += tmp; }
    }
    __syncthreads();
    int excl = ws[wid] + x - v;
    if (t < NBLK) g_bsum[t] = excl;
    if (t == NBLK - 1) g_rowptr[NN] = excl + v;
}

// scan stage 3: per-block exclusive scan + offset; rowptr/invdeg/c
__global__ void k_scan3() {
    __shared__ int ws[8];
    int t = threadIdx.x, lane = t & 31, wid = t >> 5;
    int i = blockIdx.x * 256 + t;
    int v = (i < NN) ? g_indeg[i] : 0;
    int x = v;
#pragma unroll
    for (int s = 1; s < 32; s <<= 1) {
        int tt = __shfl_up_sync(0xffffffffu, x, s);
        if (lane >= s) x += tt;
    }
    if (lane == 31) ws[wid] = x;
    __syncthreads();
    if (t == 0) {
        int acc = 0;
#pragma unroll
        for (int w = 0; w < 8; w++) { int tmp = ws[w]; ws[w] = acc; acc += tmp; }
    }
    __syncthreads();
    if (i < NN) {
        g_rowptr[i] = g_bsum[blockIdx.x] + ws[wid] + x - v;
        g_invdeg[i] = 1.0f / fmaxf((float)v, 1.0f);
        g_c[i] = (v > 0) ? 2.0f : 1.0f;
    }
}

__global__ void k_fill(const int* __restrict__ ei) {
    int e = blockIdx.x * blockDim.x + threadIdx.x;
    if (e < NE) {
        int dst = ei[NE + e];
        int p = g_rowptr[dst] + atomicAdd(&g_fill[dst], 1);
        g_csr_src[p] = ei[e];
        g_csr_eid[p] = e;
    }
}

// V[i] = (sum_{e->i} edge_attr[e]) / deg[i] -> split bf16; one warp per node
__global__ void k_v(const float* __restrict__ ea) {
    int gt = blockIdx.x * blockDim.x + threadIdx.x;
    int w = gt >> 5, lane = gt & 31;
    if (w >= NN) return;
    int s = g_rowptr[w], t = g_rowptr[w + 1];
    float4 acc = make_float4(0.f, 0.f, 0.f, 0.f);
    const float4* ea4 = (const float4*)ea;
    int p = s;
    for (; p + 1 < t; p += 2) {
        int e0 = g_csr_eid[p], e1 = g_csr_eid[p + 1];
        float4 x0 = ea4[e0 * 32 + lane];
        float4 x1 = ea4[e1 * 32 + lane];
        acc.x += x0.x + x1.x; acc.y += x0.y + x1.y;
        acc.z += x0.z + x1.z; acc.w += x0.w + x1.w;
    }
    if (p < t) {
        int e0 = g_csr_eid[p];
        float4 x0 = ea4[e0 * 32 + lane];
        acc.x += x0.x; acc.y += x0.y; acc.z += x0.z; acc.w += x0.w;
    }
    float id = g_invdeg[w];
    acc.x *= id; acc.y *= id; acc.z *= id; acc.w *= id;
    uint2 hi, lo; split4(acc, hi, lo);
    ((uint2*)g_vhi)[w * 32 + lane] = hi;
    ((uint2*)g_vlo)[w * 32 + lane] = lo;
}

// layer-0 shortcut: u = c[i] * node_emb[x[i]]
__global__ void k_u0(const float* __restrict__ emb, const int* __restrict__ x) {
    int i = blockIdx.x * blockDim.x + threadIdx.x;
    if (i >= NN * 32) return;
    int node = i >> 5, q = i & 31;
    float4 e = ((const float4*)emb)[x[node] * 32 + q];
    float c = g_c[node];
    e.x *= c; e.y *= c; e.z *= c; e.w *= c;
    uint2 hi, lo; split4(e, hi, lo);
    ((uint2*)g_uhi)[i] = hi;
    ((uint2*)g_ulo)[i] = lo;
}

// u[i] = h[i] + (sum_{e->i} h[src_e]) / deg[i] -> split bf16
__global__ void k_spmm() {
    int gt = blockIdx.x * blockDim.x + threadIdx.x;
    int w = gt >> 5, lane = gt & 31;
    if (w >= NN) return;
    int s = g_rowptr[w], t = g_rowptr[w + 1];
    float4 acc = make_float4(0.f, 0.f, 0.f, 0.f);
    const float4* h4 = (const float4*)g_h;
    int p = s;
    for (; p + 1 < t; p += 2) {
        int s0 = g_csr_src[p], s1 = g_csr_src[p + 1];
        float4 x0 = h4[s0 * 32 + lane];
        float4 x1 = h4[s1 * 32 + lane];
        acc.x += x0.x + x1.x; acc.y += x0.y + x1.y;
        acc.z += x0.z + x1.z; acc.w += x0.w + x1.w;
    }
    if (p < t) {
        int s0 = g_csr_src[p];
        float4 x0 = h4[s0 * 32 + lane];
        acc.x += x0.x; acc.y += x0.y; acc.z += x0.z; acc.w += x0.w;
    }
    float id = g_invdeg[w];
    float4 hh = h4[w * 32 + lane];
    acc.x = hh.x + acc.x * id; acc.y = hh.y + acc.y * id;
    acc.z = hh.z + acc.z * id; acc.w = hh.w + acc.w * id;
    uint2 hi, lo; split4(acc, hi, lo);
    ((uint2*)g_uhi)[w * 32 + lane] = hi;
    ((uint2*)g_ulo)[w * 32 + lane] = lo;
}

// pre-split stacked weights [W_l ; We_l] -> bf16 hi/lo, [NL][256][128]
__global__ void k_wsplit(const float* __restrict__ Ws, const float* __restrict__ Wes) {
    int i = blockIdx.x * blockDim.x + threadIdx.x;
    if (i >= NL * 256 * 128) return;
    int l = i / (256 * 128);
    int rem = i - l * 256 * 128;
    int r = rem >> 7, c = rem & 127;
    float v = (r < 128) ? Ws[l * 16384 + r * 128 + c]
                        : Wes[l * 16384 + (r - 128) * 128 + c];
    __nv_bfloat16 h = __float2bfloat16(v);
    __nv_bfloat16 lo = __float2bfloat16(v - __bfloat162float(h));
    g_Whi[i] = h;
    g_Wlo[i] = lo;
}

// h = act( [u | v] @ [W ; We] + c*b )  via bf16x3 mma.sync tensor cores
// block tile 128x128, K=256, 8 warps (warp tile 32x64), KC=32
__global__ __launch_bounds__(256) void k_gemm(int layer, const float* __restrict__ bias,
                                              int relu) {
    __shared__ __nv_bfloat16 As_hi[128][40];
    __shared__ __nv_bfloat16 As_lo[128][40];
    __shared__ __nv_bfloat16 Bs_hi[32][136];
    __shared__ __nv_bfloat16 Bs_lo[32][136];
    __shared__ float sb[128];
    int tid = threadIdx.x;
    int warp = tid >> 5, l = tid & 31;
    if (tid < 128) sb[tid] = bias[tid];
    int row0 = blockIdx.x * 128;
    int wm = (warp >> 1) * 32, wn = (warp & 1) * 64;

    float acc[2][8][4];
#pragma unroll
    for (int a = 0; a < 2; a++)
#pragma unroll
        for (int b = 0; b < 8; b++)
#pragma unroll
            for (int c = 0; c < 4; c++) acc[a][b][c] = 0.f;

    // ldmatrix lane patterns
    int rA = (l & 7) + ((l >> 3) & 1) * 8;
    int cA = (l >> 4) * 8;
    uint32_t aHi = sptr(&As_hi[wm + rA][cA]);
    uint32_t aLo = sptr(&As_lo[wm + rA][cA]);
    uint32_t bHi = sptr(&Bs_hi[rA][wn + cA]);
    uint32_t bLo = sptr(&Bs_lo[rA][wn + cA]);

    const __nv_bfloat16* Whi = g_Whi + layer * 32768;
    const __nv_bfloat16* Wlo = g_Wlo + layer * 32768;

#pragma unroll 1
    for (int kt = 0; kt < 8; kt++) {
        const __nv_bfloat16* Ahi = (kt < 4) ? g_uhi : g_vhi;
        const __nv_bfloat16* Alo = (kt < 4) ? g_ulo : g_vlo;
        int akb = (kt & 3) * 32;
        __syncthreads();
#pragma unroll
        for (int j = 0; j < 2; j++) {
            int idx = tid + 256 * j;
            int r = idx >> 2, s = idx & 3;
            int grow = row0 + r;
            int4 vh = make_int4(0, 0, 0, 0), vl = make_int4(0, 0, 0, 0);
            if (grow < NN) {
                vh = *(const int4*)&Ahi[grow * 128 + akb + s * 8];
                vl = *(const int4*)&Alo[grow * 128 + akb + s * 8];
            }
            *(int4*)&As_hi[r][s * 8] = vh;
            *(int4*)&As_lo[r][s * 8] = vl;
        }
#pragma unroll
        for (int j = 0; j < 2; j++) {
            int idx = tid + 256 * j;
            int k = idx >> 4, s = idx & 15;
            *(int4*)&Bs_hi[k][s * 8] = *(const int4*)&Whi[(kt * 32 + k) * 128 + s * 8];
            *(int4*)&Bs_lo[k][s * 8] = *(const int4*)&Wlo[(kt * 32 + k) * 128 + s * 8];
        }
        __syncthreads();

#pragma unroll
        for (int ks = 0; ks < 2; ks++) {
            int k16 = ks * 16;
            uint32_t ah[2][4], al[2][4];
#pragma unroll
            for (int mt = 0; mt < 2; mt++) {
                LDSM4(ah[mt], aHi + (mt * 16 * 40 + k16) * 2);
                LDSM4(al[mt], aLo + (mt * 16 * 40 + k16) * 2);
            }
#pragma unroll
            for (int ng = 0; ng < 4; ng++) {
                uint32_t bh[4], bl[4];
                LDSM4T(bh, bHi + (k16 * 136 + ng * 16) * 2);
                LDSM4T(bl, bLo + (k16 * 136 + ng * 16) * 2);
#pragma unroll
                for (int mt = 0; mt < 2; mt++) {
#pragma unroll
                    for (int sub = 0; sub < 2; sub++) {
                        float* C = acc[mt][ng * 2 + sub];
                        MMA(C, ah[mt], &bh[sub * 2]);
                        MMA(C, ah[mt], &bl[sub * 2]);
                        MMA(C, al[mt], &bh[sub * 2]);
                    }
                }
            }
        }
    }

    // epilogue: + c*b, relu, store fp32 h
    int g = l >> 2, tg = l & 3;
#pragma unroll
    for (int mt = 0; mt < 2; mt++) {
        int r1 = row0 + wm + mt * 16 + g;
        int r2 = r1 + 8;
        float c1 = (r1 < NN) ? g_c[r1] : 0.f;
        float c2 = (r2 < NN) ? g_c[r2] : 0.f;
#pragma unroll
        for (int nt = 0; nt < 8; nt++) {
            int col = wn + nt * 8 + tg * 2;
            float b0 = sb[col], b1 = sb[col + 1];
            float* C = acc[mt][nt];
            float v0 = C[0] + c1 * b0, v1 = C[1] + c1 * b1;
            float v2 = C[2] + c2 * b0, v3 = C[3] + c2 * b1;
            if (relu) {
                v0 = fmaxf(v0, 0.f); v1 = fmaxf(v1, 0.f);
                v2 = fmaxf(v2, 0.f); v3 = fmaxf(v3, 0.f);
            }
            if (r1 < NN) *(float2*)&g_h[r1 * 128 + col] = make_float2(v0, v1);
            if (r2 < NN) *(float2*)&g_h[r2 * 128 + col] = make_float2(v2, v3);
        }
    }
}

// ---------------- fused pooling + classifier (batch is sorted) --------------
__device__ __forceinline__ int lower_bound(const int* a, int n, int key) {
    int lo = 0, hi = n;
    while (lo < hi) {
        int mid = (lo + hi) >> 1;
        if (a[mid] < key) lo = mid + 1; else hi = mid;
    }
    return lo;
}

__global__ void k_pool_out(const int* __restrict__ batch,
                           const float* __restrict__ Wp,
                           const float* __restrict__ bp,
                           float* __restrict__ out) {
    int g = blockIdx.x, t = threadIdx.x;
    __shared__ int s_lo, s_hi;
    __shared__ float sp[128];
    if (t == 0) s_lo = lower_bound(batch, NN, g);
    if (t == 1) s_hi = lower_bound(batch, NN, g + 1);
    __syncthreads();
    int lo = s_lo, hi = s_hi;
    float sum = 0.f;
    for (int r = lo; r < hi; r++) sum += g_h[r * 128 + t];
    float inv = 1.f / fmaxf((float)(hi - lo), 1.f);
    sp[t] = sum * inv;
    __syncthreads();
    float acc = bp[t];
#pragma unroll 8
    for (int k = 0; k < 128; k++) acc = fmaf(sp[k], Wp[k * NC + t], acc);
    out[g * NC + t] = acc;
}

// ---------------- launch ----------------------------------------------------
extern "C" void kernel_launch(void* const* d_in, const int* in_sizes, int n_in,
                              void* d_out, int out_size) {
    const int*   x     = (const int*)d_in[0];
    const int*   ei    = (const int*)d_in[1];
    const float* ea    = (const float*)d_in[2];
    const int*   batch = (const int*)d_in[3];
    const float* emb   = (const float*)d_in[4];
    const float* Ws    = (const float*)d_in[5];
    const float* bs    = (const float*)d_in[6];
    const float* Wes   = (const float*)d_in[7];
    const float* Wp    = (const float*)d_in[8];
    const float* bp    = (const float*)d_in[9];
    float* out = (float*)d_out;

    k_zero<<<NBLK, 256>>>();
    k_count<<<(NE + 255) / 256, 256>>>(ei);
    k_scan1<<<NBLK, 256>>>();
    k_scan2<<<1, 256>>>();
    k_scan3<<<NBLK, 256>>>();
    k_fill<<<(NE + 255) / 256, 256>>>(ei);
    k_wsplit<<<(NL * 256 * 128 + 255) / 256, 256>>>(Ws, Wes);
    k_v<<<(NN * 32 + 255) / 256, 256>>>(ea);
    k_u0<<<(NN * 32 + 255) / 256, 256>>>(emb, x);
    for (int l = 0; l < NL; l++) {
        if (l > 0) k_spmm<<<(NN * 32 + 255) / 256, 256>>>();
        k_gemm<<<(NN + 127) / 128, 256>>>(l, bs + l * D, l < NL - 1 ? 1 : 0);
    }
    k_pool_out<<<NG, 128>>>(batch, Wp, bp, out);
}

// round 3
// speedup vs baseline: 2.0570x; 1.1966x over previous
#include <cuda_runtime.h>
#include <cuda_bf16.h>
#include <cstdint>

#define NN 50000
#define NE 640000
#define D  128
#define NG 512
#define NBLK ((NN + 255) / 256)

// dynamic smem layout for k_gemm (bytes)
#define A_HI_OFF 0        // [2][128][40] bf16 : 2*10240
#define A_LO_OFF 20480
#define B_HI_OFF 40960    // [2][32][136] bf16 : 2*8704
#define B_LO_OFF 58368
#define SB_OFF   75776    // float[128]
#define GEMM_SMEM 76288
#define ABUF 10240
#define BBUF 8704

// ---------------- scratch (static device globals) --------------------------
__device__ __align__(16) float g_h[NN * D];
__device__ __align__(16) float g_u32[NN * D];
__device__ __align__(16) __nv_bfloat16 g_uhi[NN * D];
__device__ __align__(16) __nv_bfloat16 g_ulo[NN * D];
__device__ __align__(16) __nv_bfloat16 g_vhi[NN * D];
__device__ __align__(16) __nv_bfloat16 g_vlo[NN * D];
__device__ __align__(16) __nv_bfloat16 g_Whi[4 * 256 * 128];
__device__ __align__(16) __nv_bfloat16 g_Wlo[4 * 256 * 128];
__device__ __align__(16) float g_Wcomb[256 * 128];
__device__ float g_bw[128];
__device__ float g_t0[128];
__device__ float g_invdeg[NN];
__device__ float g_c[NN];
__device__ int   g_indeg[NN];
__device__ int   g_rowptr[NN + 1];
__device__ int   g_fill[NN];
__device__ int   g_bsum[NBLK + 32];
__device__ int   g_csr_src[NE];
__device__ int   g_csr_eid[NE];

// ---------------- helpers ---------------------------------------------------
__device__ __forceinline__ unsigned short bf_bits(__nv_bfloat16 h) {
    unsigned short u; memcpy(&u, &h, 2); return u;
}
__device__ __forceinline__ void split4(float4 a, uint2& hi, uint2& lo) {
    __nv_bfloat16 h0 = __float2bfloat16(a.x), h1 = __float2bfloat16(a.y);
    __nv_bfloat16 h2 = __float2bfloat16(a.z), h3 = __float2bfloat16(a.w);
    __nv_bfloat16 l0 = __float2bfloat16(a.x - __bfloat162float(h0));
    __nv_bfloat16 l1 = __float2bfloat16(a.y - __bfloat162float(h1));
    __nv_bfloat16 l2 = __float2bfloat16(a.z - __bfloat162float(h2));
    __nv_bfloat16 l3 = __float2bfloat16(a.w - __bfloat162float(h3));
    hi.x = (unsigned)bf_bits(h0) | ((unsigned)bf_bits(h1) << 16);
    hi.y = (unsigned)bf_bits(h2) | ((unsigned)bf_bits(h3) << 16);
    lo.x = (unsigned)bf_bits(l0) | ((unsigned)bf_bits(l1) << 16);
    lo.y = (unsigned)bf_bits(l2) | ((unsigned)bf_bits(l3) << 16);
}
__device__ __forceinline__ uint32_t sptr(const void* p) {
    return (uint32_t)__cvta_generic_to_shared(p);
}

#define LDSM4(R, addr) \
    asm volatile("ldmatrix.sync.aligned.m8n8.x4.shared.b16 {%0,%1,%2,%3},[%4];" \
        : "=r"((R)[0]), "=r"((R)[1]), "=r"((R)[2]), "=r"((R)[3]) : "r"(addr))
#define LDSM4T(R, addr) \
    asm volatile("ldmatrix.sync.aligned.m8n8.x4.trans.shared.b16 {%0,%1,%2,%3},[%4];" \
        : "=r"((R)[0]), "=r"((R)[1]), "=r"((R)[2]), "=r"((R)[3]) : "r"(addr))
#define MMA(C, A, B) \
    asm volatile("mma.sync.aligned.m16n8k16.row.col.f32.bf16.bf16.f32 " \
        "{%0,%1,%2,%3},{%4,%5,%6,%7},{%8,%9},{%0,%1,%2,%3};" \
        : "+f"((C)[0]), "+f"((C)[1]), "+f"((C)[2]), "+f"((C)[3]) \
        : "r"((A)[0]), "r"((A)[1]), "r"((A)[2]), "r"((A)[3]), "r"((B)[0]), "r"((B)[1]))
#define CP16(dst, src) \
    asm volatile("cp.async.cg.shared.global [%0], [%1], 16;" :: "r"(dst), "l"(src))
#define CPCOMMIT() asm volatile("cp.async.commit_group;")
#define CPWAIT(n)  asm volatile("cp.async.wait_group %0;" :: "n"(n))

// ---------------- init / CSR build -----------------------------------------
__global__ void k_zero() {
    int i = blockIdx.x * blockDim.x + threadIdx.x;
    if (i < NN) { g_indeg[i] = 0; g_fill[i] = 0; }
}

__global__ void k_count(const int* __restrict__ ei) {
    int e = blockIdx.x * blockDim.x + threadIdx.x;
    if (e < NE) atomicAdd(&g_indeg[ei[NE + e]], 1);
}

__global__ void k_scan1() {
    __shared__ int sm[8];
    int t = threadIdx.x, lane = t & 31, wid = t >> 5;
    int i = blockIdx.x * 256 + t;
    int v = (i < NN) ? g_indeg[i] : 0;
#pragma unroll
    for (int s = 16; s > 0; s >>= 1) v += __shfl_down_sync(0xffffffffu, v, s);
    if (lane == 0) sm[wid] = v;
    __syncthreads();
    if (t == 0) {
        int s = 0;
#pragma unroll
        for (int w = 0; w < 8; w++) s += sm[w];
        g_bsum[blockIdx.x] = s;
    }
}

__global__ void k_scan2() {
    __shared__ int ws[8];
    int t = threadIdx.x, lane = t & 31, wid = t >> 5;
    int v = (t < NBLK) ? g_bsum[t] : 0;
    int x = v;
#pragma unroll
    for (int s = 1; s < 32; s <<= 1) {
        int tt = __shfl_up_sync(0xffffffffu, x, s);
        if (lane >= s) x += tt;
    }
    if (lane == 31) ws[wid] = x;
    __syncthreads();
    if (t == 0) {
        int acc = 0;
#pragma unroll
        for (int w = 0; w < 8; w++) { int tmp = ws[w]; ws[w] = acc; acc += tmp; }
    }
    __syncthreads();
    int excl = ws[wid] + x - v;
    if (t < NBLK) g_bsum[t] = excl;
    if (t == NBLK - 1) g_rowptr[NN] = excl + v;
}

__global__ void k_scan3() {
    __shared__ int ws[8];
    int t = threadIdx.x, lane = t & 31, wid = t >> 5;
    int i = blockIdx.x * 256 + t;
    int v = (i < NN) ? g_indeg[i] : 0;
    int x = v;
#pragma unroll
    for (int s = 1; s < 32; s <<= 1) {
        int tt = __shfl_up_sync(0xffffffffu, x, s);
        if (lane >= s) x += tt;
    }
    if (lane == 31) ws[wid] = x;
    __syncthreads();
    if (t == 0) {
        int acc = 0;
#pragma unroll
        for (int w = 0; w < 8; w++) { int tmp = ws[w]; ws[w] = acc; acc += tmp; }
    }
    __syncthreads();
    if (i < NN) {
        g_rowptr[i] = g_bsum[blockIdx.x] + ws[wid] + x - v;
        g_invdeg[i] = 1.0f / fmaxf((float)v, 1.0f);
        g_c[i] = (v > 0) ? 2.0f : 1.0f;
    }
}

__global__ void k_fill(const int* __restrict__ ei) {
    int e = blockIdx.x * blockDim.x + threadIdx.x;
    if (e < NE) {
        int dst = ei[NE + e];
        int p = g_rowptr[dst] + atomicAdd(&g_fill[dst], 1);
        g_csr_src[p] = ei[e];
        g_csr_eid[p] = e;
    }
}

// V[i] = (sum_{e->i} edge_attr[e]) / deg[i] -> split bf16
__global__ void k_v(const float* __restrict__ ea) {
    int gt = blockIdx.x * blockDim.x + threadIdx.x;
    int w = gt >> 5, lane = gt & 31;
    if (w >= NN) return;
    int s = g_rowptr[w], t = g_rowptr[w + 1];
    float4 acc = make_float4(0.f, 0.f, 0.f, 0.f);
    const float4* ea4 = (const float4*)ea;
    int p = s;
    for (; p + 1 < t; p += 2) {
        int e0 = g_csr_eid[p], e1 = g_csr_eid[p + 1];
        float4 x0 = ea4[e0 * 32 + lane];
        float4 x1 = ea4[e1 * 32 + lane];
        acc.x += x0.x + x1.x; acc.y += x0.y + x1.y;
        acc.z += x0.z + x1.z; acc.w += x0.w + x1.w;
    }
    if (p < t) {
        int e0 = g_csr_eid[p];
        float4 x0 = ea4[e0 * 32 + lane];
        acc.x += x0.x; acc.y += x0.y; acc.z += x0.z; acc.w += x0.w;
    }
    float id = g_invdeg[w];
    acc.x *= id; acc.y *= id; acc.z *= id; acc.w *= id;
    uint2 hi, lo; split4(acc, hi, lo);
    ((uint2*)g_vhi)[w * 32 + lane] = hi;
    ((uint2*)g_vlo)[w * 32 + lane] = lo;
}

// u = h + (sum h[src])/deg -> split bf16 (mid layers)
__global__ void k_spmm_split() {
    int gt = blockIdx.x * blockDim.x + threadIdx.x;
    int w = gt >> 5, lane = gt & 31;
    if (w >= NN) return;
    int s = g_rowptr[w], t = g_rowptr[w + 1];
    float4 acc = make_float4(0.f, 0.f, 0.f, 0.f);
    const float4* h4 = (const float4*)g_h;
    int p = s;
    for (; p + 1 < t; p += 2) {
        int s0 = g_csr_src[p], s1 = g_csr_src[p + 1];
        float4 x0 = h4[s0 * 32 + lane];
        float4 x1 = h4[s1 * 32 + lane];
        acc.x += x0.x + x1.x; acc.y += x0.y + x1.y;
        acc.z += x0.z + x1.z; acc.w += x0.w + x1.w;
    }
    if (p < t) {
        int s0 = g_csr_src[p];
        float4 x0 = h4[s0 * 32 + lane];
        acc.x += x0.x; acc.y += x0.y; acc.z += x0.z; acc.w += x0.w;
    }
    float id = g_invdeg[w];
    float4 hh = h4[w * 32 + lane];
    acc.x = hh.x + acc.x * id; acc.y = hh.y + acc.y * id;
    acc.z = hh.z + acc.z * id; acc.w = hh.w + acc.w * id;
    uint2 hi, lo; split4(acc, hi, lo);
    ((uint2*)g_uhi)[w * 32 + lane] = hi;
    ((uint2*)g_ulo)[w * 32 + lane] = lo;
}

// u = h + (sum h[src])/deg -> fp32 (final layer, feeds pooled path)
__global__ void k_spmm_f32() {
    int gt = blockIdx.x * blockDim.x + threadIdx.x;
    int w = gt >> 5, lane = gt & 31;
    if (w >= NN) return;
    int s = g_rowptr[w], t = g_rowptr[w + 1];
    float4 acc = make_float4(0.f, 0.f, 0.f, 0.f);
    const float4* h4 = (const float4*)g_h;
    int p = s;
    for (; p + 1 < t; p += 2) {
        int s0 = g_csr_src[p], s1 = g_csr_src[p + 1];
        float4 x0 = h4[s0 * 32 + lane];
        float4 x1 = h4[s1 * 32 + lane];
        acc.x += x0.x + x1.x; acc.y += x0.y + x1.y;
        acc.z += x0.z + x1.z; acc.w += x0.w + x1.w;
    }
    if (p < t) {
        int s0 = g_csr_src[p];
        float4 x0 = h4[s0 * 32 + lane];
        acc.x += x0.x; acc.y += x0.y; acc.z += x0.z; acc.w += x0.w;
    }
    float id = g_invdeg[w];
    float4 hh = h4[w * 32 + lane];
    acc.x = hh.x + acc.x * id; acc.y = hh.y + acc.y * id;
    acc.z = hh.z + acc.z * id; acc.w = hh.w + acc.w * id;
    ((float4*)g_u32)[w * 32 + lane] = acc;
}

// pre-split stacked weights [W_l ; We_l] (layers 0..3)
__global__ void k_wsplit(const float* __restrict__ Ws, const float* __restrict__ Wes) {
    int i = blockIdx.x * blockDim.x + threadIdx.x;
    if (i >= 4 * 256 * 128) return;
    int l = i / (256 * 128);
    int rem = i - l * 256 * 128;
    int r = rem >> 7, c = rem & 127;
    float v = (r < 128) ? Ws[l * 16384 + r * 128 + c]
                        : Wes[l * 16384 + (r - 128) * 128 + c];
    __nv_bfloat16 h = __float2bfloat16(v);
    __nv_bfloat16 lo = __float2bfloat16(v - __bfloat162float(h));
    g_Whi[i] = h;
    g_Wlo[i] = lo;
}

// r0 + b0 : rank-1 layer-0 shortcut  (h0 rows are all node_emb[0])
__global__ void k_r0(const float* __restrict__ emb, const float* __restrict__ bs,
                     const float* __restrict__ Ws) {
    int t = threadIdx.x;
    float acc = bs[t];
#pragma unroll 8
    for (int k = 0; k < 128; k++) acc = fmaf(emb[k], Ws[k * 128 + t], acc);
    g_t0[t] = acc;
}

// Wcomb = [W4;We4] @ Wp  (256x128), bw = b4 @ Wp
__global__ void k_comb(const float* __restrict__ Ws, const float* __restrict__ Wes,
                       const float* __restrict__ bs, const float* __restrict__ Wp) {
    if (blockIdx.x == 128) {
        int t = threadIdx.x;
        if (t < 128) {
            float acc = 0.f;
#pragma unroll 8
            for (int k = 0; k < 128; k++) acc = fmaf(bs[4 * 128 + k], Wp[k * 128 + t], acc);
            g_bw[t] = acc;
        }
        return;
    }
    int i = blockIdx.x * 256 + threadIdx.x;
    int r = i >> 7, c = i & 127;
    const float* Wrow = (r < 128) ? (Ws + 4 * 16384 + r * 128)
                                  : (Wes + 4 * 16384 + (r - 128) * 128);
    float acc = 0.f;
#pragma unroll 8
    for (int k = 0; k < 128; k++) acc = fmaf(Wrow[k], Wp[k * 128 + c], acc);
    g_Wcomb[i] = acc;
}

// h = relu( [u|v] @ [W;We] + c*t )  — bf16x3 mma, cp.async double-buffered.
// block 128x128, K = 32*(8-first_stage), 8 warps, warp tile 32x64.
__global__ __launch_bounds__(256) void k_gemm(int layer, int first_stage,
                                              const float* __restrict__ tvec) {
    extern __shared__ char sm_[];
    __nv_bfloat16* As_hi = (__nv_bfloat16*)(sm_ + A_HI_OFF);
    __nv_bfloat16* As_lo = (__nv_bfloat16*)(sm_ + A_LO_OFF);
    __nv_bfloat16* Bs_hi = (__nv_bfloat16*)(sm_ + B_HI_OFF);
    __nv_bfloat16* Bs_lo = (__nv_bfloat16*)(sm_ + B_LO_OFF);
    float* sb = (float*)(sm_ + SB_OFF);

    int tid = threadIdx.x;
    int warp = tid >> 5, l = tid & 31;
    if (tid < 128) sb[tid] = tvec ? tvec[tid] : g_t0[tid];
    int row0 = blockIdx.x * 128;
    int wm = (warp >> 1) * 32, wn = (warp & 1) * 64;

    const __nv_bfloat16* Whi = g_Whi + layer * 32768;
    const __nv_bfloat16* Wlo = g_Wlo + layer * 32768;

    // cp.async thread mappings
    int ar = tid >> 1, asc = (tid & 1) * 2;          // A: 128 rows x 4 chunks; 2 chunks/thread
    int bk = tid >> 3, bsc = (tid & 7) * 2;          // B: 32 rows x 16 chunks; 2 chunks/thread

    auto issue = [&](int s, int buf) {
        const __nv_bfloat16* Ahi = (s < 4) ? g_uhi : g_vhi;
        const __nv_bfloat16* Alo = (s < 4) ? g_ulo : g_vlo;
        int akb = (s & 3) * 32;
        int grow = row0 + ar; if (grow >= NN) grow = NN - 1;
        const __nv_bfloat16* ah = Ahi + grow * 128 + akb + asc * 8;
        const __nv_bfloat16* al = Alo + grow * 128 + akb + asc * 8;
        uint32_t dh = sptr(As_hi + (buf * 128 + ar) * 40 + asc * 8);
        uint32_t dl = sptr(As_lo + (buf * 128 + ar) * 40 + asc * 8);
        CP16(dh, ah); CP16(dh + 16, ah + 8);
        CP16(dl, al); CP16(dl + 16, al + 8);
        const __nv_bfloat16* bh = Whi + (s * 32 + bk) * 128 + bsc * 8;
        const __nv_bfloat16* bl = Wlo + (s * 32 + bk) * 128 + bsc * 8;
        uint32_t eh = sptr(Bs_hi + (buf * 32 + bk) * 136 + bsc * 8);
        uint32_t el = sptr(Bs_lo + (buf * 32 + bk) * 136 + bsc * 8);
        CP16(eh, bh); CP16(eh + 16, bh + 8);
        CP16(el, bl); CP16(el + 16, bl + 8);
        CPCOMMIT();
    };

    float acc[2][8][4];
#pragma unroll
    for (int a = 0; a < 2; a++)
#pragma unroll
        for (int b = 0; b < 8; b++)
#pragma unroll
            for (int c = 0; c < 4; c++) acc[a][b][c] = 0.f;

    int rA = (l & 7) + ((l >> 3) & 1) * 8;
    int cA = (l >> 4) * 8;
    uint32_t aHi0 = sptr(As_hi + (wm + rA) * 40 + cA);
    uint32_t aLo0 = sptr(As_lo + (wm + rA) * 40 + cA);
    uint32_t bHi0 = sptr(Bs_hi + rA * 136 + wn + cA);
    uint32_t bLo0 = sptr(Bs_lo + rA * 136 + wn + cA);

    issue(first_stage, 0);
#pragma unroll 1
    for (int s = first_stage; s < 8; s++) {
        int buf = (s - first_stage) & 1;
        if (s + 1 < 8) issue(s + 1, buf ^ 1);
        if (s + 1 < 8) { CPWAIT(1); } else { CPWAIT(0); }
        __syncthreads();

        uint32_t aHi = aHi0 + buf * ABUF, aLo = aLo0 + buf * ABUF;
        uint32_t bHi = bHi0 + buf * BBUF, bLo = bLo0 + buf * BBUF;
#pragma unroll
        for (int ks = 0; ks < 2; ks++) {
            int k16 = ks * 16;
            uint32_t ah[2][4], al[2][4];
#pragma unroll
            for (int mt = 0; mt < 2; mt++) {
                LDSM4(ah[mt], aHi + (mt * 16 * 40 + k16) * 2);
                LDSM4(al[mt], aLo + (mt * 16 * 40 + k16) * 2);
            }
#pragma unroll
            for (int ng = 0; ng < 4; ng++) {
                uint32_t bh[4], bl[4];
                LDSM4T(bh, bHi + (k16 * 136 + ng * 16) * 2);
                LDSM4T(bl, bLo + (k16 * 136 + ng * 16) * 2);
#pragma unroll
                for (int mt = 0; mt < 2; mt++) {
#pragma unroll
                    for (int sub = 0; sub < 2; sub++) {
                        float* C = acc[mt][ng * 2 + sub];
                        MMA(C, ah[mt], &bh[sub * 2]);
                        MMA(C, ah[mt], &bl[sub * 2]);
                        MMA(C, al[mt], &bh[sub * 2]);
                    }
                }
            }
        }
        __syncthreads();
    }

    // epilogue: h = relu(acc + c * t)
    int g = l >> 2, tg = l & 3;
#pragma unroll
    for (int mt = 0; mt < 2; mt++) {
        int r1 = row0 + wm + mt * 16 + g;
        int r2 = r1 + 8;
        float c1 = (r1 < NN) ? g_c[r1] : 0.f;
        float c2 = (r2 < NN) ? g_c[r2] : 0.f;
#pragma unroll
        for (int nt = 0; nt < 8; nt++) {
            int col = wn + nt * 8 + tg * 2;
            float b0 = sb[col], b1 = sb[col + 1];
            float* C = acc[mt][nt];
            float v0 = fmaxf(C[0] + c1 * b0, 0.f), v1 = fmaxf(C[1] + c1 * b1, 0.f);
            float v2 = fmaxf(C[2] + c2 * b0, 0.f), v3 = fmaxf(C[3] + c2 * b1, 0.f);
            if (r1 < NN) *(float2*)&g_h[r1 * 128 + col] = make_float2(v0, v1);
            if (r2 < NN) *(float2*)&g_h[r2 * 128 + col] = make_float2(v2, v3);
        }
    }
}

// ---------------- fused pool + collapsed last layer + classifier ------------
__device__ __forceinline__ int lower_bound(const int* a, int n, int key) {
    int lo = 0, hi = n;
    while (lo < hi) {
        int mid = (lo + hi) >> 1;
        if (a[mid] < key) lo = mid + 1; else hi = mid;
    }
    return lo;
}

__global__ void k_pool_out(const int* __restrict__ batch,
                           const float* __restrict__ bp,
                           float* __restrict__ out) {
    int g = blockIdx.x, t = threadIdx.x;
    __shared__ int s_lo, s_hi;
    __shared__ float sp[256];
    __shared__ float spc[256];
    if (t == 0) s_lo = lower_bound(batch, NN, g);
    if (t == 1) s_hi = lower_bound(batch, NN, g + 1);
    __syncthreads();
    int lo = s_lo, hi = s_hi;
    float sum = 0.f;
    if (t < 128) {
        for (int r = lo; r < hi; r++) sum += g_u32[r * 128 + t];
    } else {
        int q = t - 128;
        for (int r = lo; r < hi; r++)
            sum += __bfloat162float(g_vhi[r * 128 + q]) + __bfloat162float(g_vlo[r * 128 + q]);
    }
    float csum = 0.f;
    for (int r = lo + t; r < hi; r += 256) csum += g_c[r];
    float inv = 1.f / fmaxf((float)(hi - lo), 1.f);
    sp[t] = sum * inv;
    spc[t] = csum;
    __syncthreads();
#pragma unroll
    for (int s = 128; s > 0; s >>= 1) {
        if (t < s) spc[t] += spc[t + s];
        __syncthreads();
    }
    float pcm = spc[0] * inv;
    if (t < 128) {
        float acc = fmaf(pcm, g_bw[t], bp[t]);
#pragma unroll 8
        for (int k = 0; k < 256; k++) acc = fmaf(sp[k], g_Wcomb[k * 128 + t], acc);
        out[g * 128 + t] = acc;
    }
}

// ---------------- launch ----------------------------------------------------
extern "C" void kernel_launch(void* const* d_in, const int* in_sizes, int n_in,
                              void* d_out, int out_size) {
    const int*   ei    = (const int*)d_in[1];
    const float* ea    = (const float*)d_in[2];
    const int*   batch = (const int*)d_in[3];
    const float* emb   = (const float*)d_in[4];
    const float* Ws    = (const float*)d_in[5];
    const float* bs    = (const float*)d_in[6];
    const float* Wes   = (const float*)d_in[7];
    const float* Wp    = (const float*)d_in[8];
    const float* bp    = (const float*)d_in[9];
    float* out = (float*)d_out;

    static bool attr_done = false;
    if (!attr_done) {
        cudaFuncSetAttribute(k_gemm, cudaFuncAttributeMaxDynamicSharedMemorySize,
                             GEMM_SMEM);
        attr_done = true;
    }

    k_zero<<<NBLK, 256>>>();
    k_count<<<(NE + 255) / 256, 256>>>(ei);
    k_scan1<<<NBLK, 256>>>();
    k_scan2<<<1, 256>>>();
    k_scan3<<<NBLK, 256>>>();
    k_fill<<<(NE + 255) / 256, 256>>>(ei);
    k_wsplit<<<(4 * 256 * 128 + 255) / 256, 256>>>(Ws, Wes);
    k_r0<<<1, 128>>>(emb, bs, Ws);
    k_comb<<<129, 256>>>(Ws, Wes, bs, Wp);
    k_v<<<(NN * 32 + 255) / 256, 256>>>(ea);
    // layer 0: rank-1 shortcut, K=128 (v@We0 only)
    k_gemm<<<(NN + 127) / 128, 256, GEMM_SMEM>>>(0, 4, nullptr);
    // layers 1..3
    for (int l = 1; l < 4; l++) {
        k_spmm_split<<<(NN * 32 + 255) / 256, 256>>>();
        k_gemm<<<(NN + 127) / 128, 256, GEMM_SMEM>>>(l, 0, bs + l * 128);
    }
    // layer 4 collapsed into pooled path
    k_spmm_f32<<<(NN * 32 + 255) / 256, 256>>>();
    k_pool_out<<<NG, 256>>>(batch, bp, out);
}